// round 12
// baseline (speedup 1.0000x reference)
#include <cuda_runtime.h>

// Problem constants
#define BB 128
#define TT 2048
#define LL 8              // timesteps per chunk
#define CC (TT / LL)      // 256 chunks per batch
#define NM (BB * TT)      // 262144 matrices total
#define DT 0.02f

// g_U holds intra-chunk PREFIX products: entry (b, c*8+l) = U_l...U_0 of chunk c.
__device__ __align__(128) float4 g_U[(size_t)NM * 8];        // 33.5 MB
__device__ __align__(128) float4 g_S[(size_t)BB * CC * 8];   // incoming state per chunk

// ---------------------------------------------------------------------------
// Packed f32x2 primitives (FFMA2 — only reachable via PTX)
typedef unsigned long long u64p;

__device__ __forceinline__ u64p pk2(float x, float y) {
    u64p r; asm("mov.b64 %0, {%1, %2};" : "=l"(r) : "f"(x), "f"(y)); return r;
}
__device__ __forceinline__ void upk2(u64p v, float& x, float& y) {
    asm("mov.b64 {%0, %1}, %2;" : "=f"(x), "=f"(y) : "l"(v));
}
__device__ __forceinline__ u64p psplat(float a) { return pk2(a, a); }
__device__ __forceinline__ u64p pfma(u64p a, u64p b, u64p c) {
    u64p r; asm("fma.rn.f32x2 %0, %1, %2, %3;" : "=l"(r) : "l"(a), "l"(b), "l"(c)); return r;
}
__device__ __forceinline__ u64p pmul(u64p a, u64p b) {
    u64p r; asm("mul.rn.f32x2 %0, %1, %2;" : "=l"(r) : "l"(a), "l"(b)); return r;
}
__device__ __forceinline__ u64p padd(u64p a, u64p b) {
    u64p r; asm("add.rn.f32x2 %0, %1, %2;" : "=l"(r) : "l"(a), "l"(b)); return r;
}

struct PRow { u64p r01, r23, i01, i23; };

__device__ __forceinline__ void caccum(float a, float b, const PRow& y, PRow& z) {
    u64p sa = psplat(a), sb = psplat(b), snb = psplat(-b);
    z.r01 = pfma(sa, y.r01, pfma(snb, y.i01, z.r01));
    z.r23 = pfma(sa, y.r23, pfma(snb, y.i23, z.r23));
    z.i01 = pfma(sa, y.i01, pfma(sb, y.r01, z.i01));
    z.i23 = pfma(sa, y.i23, pfma(sb, y.r23, z.i23));
}

// z_row = x_row * Y — DUAL-ACCUMULATOR version (halves the dependency chain:
// two independent 4-deep pfma chains + one padd, instead of one 8-deep chain)
__device__ __forceinline__ PRow prow_mm(const PRow& xrow, const PRow* __restrict__ y) {
    PRow z1, z2;
    z1.r01 = pk2(0, 0); z1.r23 = pk2(0, 0); z1.i01 = pk2(0, 0); z1.i23 = pk2(0, 0);
    z2.r01 = pk2(0, 0); z2.r23 = pk2(0, 0); z2.i01 = pk2(0, 0); z2.i23 = pk2(0, 0);
    float e0, e1, e2, e3, f0, f1, f2, f3;
    upk2(xrow.r01, e0, e1); upk2(xrow.r23, e2, e3);
    upk2(xrow.i01, f0, f1); upk2(xrow.i23, f2, f3);
    caccum(e0, f0, y[0], z1);
    caccum(e1, f1, y[1], z2);
    caccum(e2, f2, y[2], z1);
    caccum(e3, f3, y[3], z2);
    PRow z;
    z.r01 = padd(z1.r01, z2.r01);
    z.r23 = padd(z1.r23, z2.r23);
    z.i01 = padd(z1.i01, z2.i01);
    z.i23 = padd(z1.i23, z2.i23);
    return z;
}

// ---------------------------------------------------------------------------
// Scalar helpers
__device__ __forceinline__ void cax4(float a, float b, float4 cr, float4 ci,
                                     float4& accr, float4& acci) {
    accr.x = fmaf(a, cr.x, fmaf(-b, ci.x, accr.x));
    acci.x = fmaf(a, ci.x, fmaf( b, cr.x, acci.x));
    accr.y = fmaf(a, cr.y, fmaf(-b, ci.y, accr.y));
    acci.y = fmaf(a, ci.y, fmaf( b, cr.y, acci.y));
    accr.z = fmaf(a, cr.z, fmaf(-b, ci.z, accr.z));
    acci.z = fmaf(a, ci.z, fmaf( b, cr.z, acci.z));
    accr.w = fmaf(a, cr.w, fmaf(-b, ci.w, accr.w));
    acci.w = fmaf(a, ci.w, fmaf( b, cr.w, acci.w));
}

// shuffle one full float4-pair row from lane `src`
__device__ __forceinline__ void shfl_row(float4 pr, float4 pim, int src,
                                         float4& outr, float4& outi) {
    outr.x = __shfl_sync(0xffffffffu, pr.x, src);
    outr.y = __shfl_sync(0xffffffffu, pr.y, src);
    outr.z = __shfl_sync(0xffffffffu, pr.z, src);
    outr.w = __shfl_sync(0xffffffffu, pr.w, src);
    outi.x = __shfl_sync(0xffffffffu, pim.x, src);
    outi.y = __shfl_sync(0xffffffffu, pim.y, src);
    outi.z = __shfl_sync(0xffffffffu, pim.z, src);
    outi.w = __shfl_sync(0xffffffffu, pim.w, src);
}

// ---------------------------------------------------------------------------
// K0: U = expm(-i*dt*H) (degree-4 Taylor, packed f32x2), then a Kogge-Stone
// INCLUSIVE SCAN over the 8 lanes of each chunk (shfl_up, no swaps):
// lane l ends with prefix_l = U_l ... U_0, stored to g_U.
// prefix_7 doubles as the chunk product consumed by k_scan. No smem/barriers.
__global__ void __launch_bounds__(128, 6) k_expm(const float* __restrict__ hr_g,
                                                 const float* __restrict__ hi_g) {
    int tid = threadIdx.x;
    int idx = blockIdx.x * 128 + tid;
    int el = tid & 7;

    const float4* hr4 = reinterpret_cast<const float4*>(hr_g) + (size_t)idx * 4;
    const float4* hi4 = reinterpret_cast<const float4*>(hi_g) + (size_t)idx * 4;

    // A = dt*hi - i*dt*hr
    PRow A[4];
    const u64p pdt = psplat(DT), pndt = psplat(-DT);
#pragma unroll
    for (int i = 0; i < 4; ++i) {
        float4 r = hr4[i], m = hi4[i];
        A[i].r01 = pmul(pdt,  pk2(m.x, m.y));
        A[i].r23 = pmul(pdt,  pk2(m.z, m.w));
        A[i].i01 = pmul(pndt, pk2(r.x, r.y));
        A[i].i23 = pmul(pndt, pk2(r.z, r.w));
    }

    // B = A^2 (row-wise, dual-accumulator)
    PRow B[4];
#pragma unroll
    for (int i = 0; i < 4; ++i) B[i] = prow_mm(A[i], A);

    // E = A + M·B, M = I/2 + A/6 + B/24 built row-by-row (A,B commute)
    const u64p c6 = psplat(1.0f / 6.0f), c24 = psplat(1.0f / 24.0f);
#pragma unroll
    for (int i = 0; i < 4; ++i) {
        PRow m;
        m.r01 = pfma(c6, A[i].r01, pmul(c24, B[i].r01));
        m.r23 = pfma(c6, A[i].r23, pmul(c24, B[i].r23));
        m.i01 = pfma(c6, A[i].i01, pmul(c24, B[i].i01));
        m.i23 = pfma(c6, A[i].i23, pmul(c24, B[i].i23));
        if (i == 0) m.r01 = padd(m.r01, pk2(0.5f, 0.0f));
        if (i == 1) m.r01 = padd(m.r01, pk2(0.0f, 0.5f));
        if (i == 2) m.r23 = padd(m.r23, pk2(0.5f, 0.0f));
        if (i == 3) m.r23 = padd(m.r23, pk2(0.0f, 0.5f));
        PRow t = prow_mm(m, B);        // m · B (dual-accumulator)
        A[i].r01 = padd(A[i].r01, t.r01);
        A[i].r23 = padd(A[i].r23, t.r23);
        A[i].i01 = padd(A[i].i01, t.i01);
        A[i].i23 = padd(A[i].i23, t.i23);
    }
    A[0].r01 = padd(A[0].r01, pk2(1.0f, 0.0f));
    A[1].r01 = padd(A[1].r01, pk2(0.0f, 1.0f));
    A[2].r23 = padd(A[2].r23, pk2(1.0f, 0.0f));
    A[3].r23 = padd(A[3].r23, pk2(0.0f, 1.0f));

    // ---- Kogge-Stone inclusive scan across the 8-lane chunk group.
    // Round d: lanes el>=d do A = A(newer, left) * Q(from lane el-d, right).
#pragma unroll
    for (int d = 1; d < 8; d <<= 1) {
        PRow Q[4];
#pragma unroll
        for (int i = 0; i < 4; ++i) {
            Q[i].r01 = __shfl_up_sync(0xffffffffu, A[i].r01, d, 8);
            Q[i].r23 = __shfl_up_sync(0xffffffffu, A[i].r23, d, 8);
            Q[i].i01 = __shfl_up_sync(0xffffffffu, A[i].i01, d, 8);
            Q[i].i23 = __shfl_up_sync(0xffffffffu, A[i].i23, d, 8);
        }
        if (el >= d) {
#pragma unroll
            for (int i = 0; i < 4; ++i) A[i] = prow_mm(A[i], Q);
        }
    }

    // store prefix to g_U (planar: re[16] then im[16]) — coalesced
    {
        float4* Up = g_U + (size_t)idx * 8;
#pragma unroll
        for (int i = 0; i < 4; ++i) {
            float x0, x1, x2, x3;
            upk2(A[i].r01, x0, x1); upk2(A[i].r23, x2, x3);
            Up[i] = make_float4(x0, x1, x2, x3);
        }
#pragma unroll
        for (int i = 0; i < 4; ++i) {
            float x0, x1, x2, x3;
            upk2(A[i].i01, x0, x1); upk2(A[i].i23, x2, x3);
            Up[4 + i] = make_float4(x0, x1, x2, x3);
        }
    }
}

// ---------------------------------------------------------------------------
// K2: TWO-LEVEL row-parallel scan per batch. 1024 threads = 256 chunks x 4 rows.
// Chunk products are read from g_U at t = e*8+7 (prefix_7 of each chunk).
#define TOFF 288   // T_B offset (T matrices stride 9 quads; 32*9=288 per buffer)

__global__ void __launch_bounds__(1024) k_scan(const float* __restrict__ s0r_g,
                                               const float* __restrict__ s0i_g) {
    __shared__ float4 sh[CC * 12];   // 48KB; quads [0,576) double as T_A/T_B
    int b = blockIdx.x;
    int tid = threadIdx.x;
    int e = tid >> 2, i = tid & 3;
    int lane = tid & 31;
    int el = lane >> 2;              // local chunk within warp (0..7)
    int g = e >> 3;                  // group (= warp id, 0..31)

    const float4* Pg = g_U + ((size_t)b * TT + (size_t)e * LL + (LL - 1)) * 8;
    float4 pr = Pg[i], pim = Pg[4 + i];

    // ---- L1: warp-local KS over 8 (rows fetched via shfl)
#pragma unroll
    for (int d = 1; d < 8; d <<= 1) {
        int srcb = ((el >= d) ? (el - d) : 0) << 2;
        float4 l0r, l0i, l1r, l1i, l2r, l2i, l3r, l3i;
        shfl_row(pr, pim, srcb + 0, l0r, l0i);
        shfl_row(pr, pim, srcb + 1, l1r, l1i);
        shfl_row(pr, pim, srcb + 2, l2r, l2i);
        shfl_row(pr, pim, srcb + 3, l3r, l3i);
        if (el >= d) {
            float4 nr = make_float4(0, 0, 0, 0), ni = make_float4(0, 0, 0, 0);
            cax4(pr.x, pim.x, l0r, l0i, nr, ni);
            cax4(pr.y, pim.y, l1r, l1i, nr, ni);
            cax4(pr.z, pim.z, l2r, l2i, nr, ni);
            cax4(pr.w, pim.w, l3r, l3i, nr, ni);
            pr = nr; pim = ni;
        }
    }

    // ---- publish group totals (el==7) into T_A (stride 9 quads per matrix)
    if (el == 7) {
        sh[g * 9 + i] = pr;
        sh[g * 9 + 4 + i] = pim;
    }
    __syncthreads();

    // ---- L2: KS over 32 totals, 128 threads, 5 rounds, double-buffered
    if (tid < 128) {
        int g2 = tid >> 2, i2 = tid & 3;
        int rb = 0;
#pragma unroll
        for (int d = 1; d < 32; d <<= 1) {
            const float4* src = sh + rb;
            float4* dst = sh + (TOFF - rb);
            float4 qr = src[g2 * 9 + i2], qi = src[g2 * 9 + 4 + i2];
            if (g2 >= d) {
                const float4* nb = src + (size_t)(g2 - d) * 9;
                float4 nr = make_float4(0, 0, 0, 0), ni = make_float4(0, 0, 0, 0);
                cax4(qr.x, qi.x, nb[0], nb[4], nr, ni);
                cax4(qr.y, qi.y, nb[1], nb[5], nr, ni);
                cax4(qr.z, qi.z, nb[2], nb[6], nr, ni);
                cax4(qr.w, qi.w, nb[3], nb[7], nr, ni);
                qr = nr; qi = ni;
            }
            dst[g2 * 9 + i2] = qr;
            dst[g2 * 9 + 4 + i2] = qi;
            asm volatile("bar.sync 1, 128;" ::: "memory");
            rb = TOFF - rb;
        }
    }
    __syncthreads();
    // G (inclusive group prefixes) now at sh + TOFF

    // ---- inclusive prefix: Q_e * G_{g-1}
    if (g > 0) {
        const float4* nb = sh + TOFF + (size_t)(g - 1) * 9;
        float4 nr = make_float4(0, 0, 0, 0), ni = make_float4(0, 0, 0, 0);
        cax4(pr.x, pim.x, nb[0], nb[4], nr, ni);
        cax4(pr.y, pim.y, nb[1], nb[5], nr, ni);
        cax4(pr.z, pim.z, nb[2], nb[6], nr, ni);
        cax4(pr.w, pim.w, nb[3], nb[7], nr, ni);
        pr = nr; pim = ni;
    }
    __syncthreads();   // everyone done reading T before overwriting sh below

    // ---- publish inclusive rows (XOR-swizzled layout)
    int es = e & 7;
    {
        float4* me = sh + e * 12;
        me[i ^ es] = pr;
        me[(4 + i) ^ es] = pim;
    }
    __syncthreads();

    // ---- V_e = Prefix_{e-1} * S0  (V_0 = S0)
    const float4* r4 = reinterpret_cast<const float4*>(s0r_g) + (size_t)b * 4;
    const float4* i4 = reinterpret_cast<const float4*>(s0i_g) + (size_t)b * 4;
    float4 s0r0 = r4[0], s0r1 = r4[1], s0r2 = r4[2], s0r3 = r4[3];
    float4 s0i0 = i4[0], s0i1 = i4[1], s0i2 = i4[2], s0i3 = i4[3];

    float4 vr, vi;
    if (e == 0) {
        vr = (i == 0) ? s0r0 : (i == 1) ? s0r1 : (i == 2) ? s0r2 : s0r3;
        vi = (i == 0) ? s0i0 : (i == 1) ? s0i1 : (i == 2) ? s0i2 : s0i3;
    } else {
        int ens = (e - 1) & 7;
        const float4* nb = sh + (e - 1) * 12;
        float4 qr = nb[i ^ ens];
        float4 qi = nb[(4 + i) ^ ens];
        vr = make_float4(0, 0, 0, 0); vi = make_float4(0, 0, 0, 0);
        cax4(qr.x, qi.x, s0r0, s0i0, vr, vi);
        cax4(qr.y, qi.y, s0r1, s0i1, vr, vi);
        cax4(qr.z, qi.z, s0r2, s0i2, vr, vi);
        cax4(qr.w, qi.w, s0r3, s0i3, vr, vi);
    }
    float4* Sg = g_S + ((size_t)b * CC + e) * 8;
    Sg[i] = vr;
    Sg[4 + i] = vi;
}

// ---------------------------------------------------------------------------
// K3: apply via prefixes — 8 INDEPENDENT products per thread, no smem/sync.
// Thread = (chunk gidx, row i), batch-major: warp = 8 consecutive b, same c.
// S_{c*8+l} = prefix_l * V_c ; row i needs only prefix row i and full V.
__global__ void __launch_bounds__(128) k_apply(float* __restrict__ out) {
    int tid = threadIdx.x;
    int cl = tid >> 2, i = tid & 3;
    int gidx = blockIdx.x * 32 + cl;         // b-fast ordering
    int b = gidx & (BB - 1);
    int c = gidx >> 7;                       // / BB
    int idx = b * CC + c;

    // full incoming state V (group-broadcast loads, L1-served)
    const float4* Vg = g_S + (size_t)idx * 8;
    float4 v0r = Vg[0], v1r = Vg[1], v2r = Vg[2], v3r = Vg[3];
    float4 v0i = Vg[4], v1i = Vg[5], v2i = Vg[6], v3i = Vg[7];

    const float4* Ug = g_U + ((size_t)b * TT + (size_t)c * LL) * 8;
    const size_t imag_off = (size_t)TT * BB * 16;
    float* ob = out + (((size_t)c * LL) * BB + b) * 16 + i * 4;

#pragma unroll
    for (int l = 0; l < LL; ++l) {
        float4 pr = Ug[l * 8 + i];           // prefix_l row i, real
        float4 pi = Ug[l * 8 + 4 + i];       // imag

        float4 nr = make_float4(0, 0, 0, 0), ni = make_float4(0, 0, 0, 0);
        cax4(pr.x, pi.x, v0r, v0i, nr, ni);
        cax4(pr.y, pi.y, v1r, v1i, nr, ni);
        cax4(pr.z, pi.z, v2r, v2i, nr, ni);
        cax4(pr.w, pi.w, v3r, v3i, nr, ni);

        float* op = ob + (size_t)l * BB * 16;
        __stcs(reinterpret_cast<float4*>(op), nr);
        __stcs(reinterpret_cast<float4*>(op + imag_off), ni);
    }
}

// ---------------------------------------------------------------------------
extern "C" void kernel_launch(void* const* d_in, const int* in_sizes, int n_in,
                              void* d_out, int out_size) {
    const float* h_real = (const float*)d_in[0];
    const float* h_imag = (const float*)d_in[1];
    const float* s_real = (const float*)d_in[2];
    const float* s_imag = (const float*)d_in[3];
    float* out = (float*)d_out;

    k_expm<<<NM / 128, 128>>>(h_real, h_imag);
    k_scan<<<BB, CC * 4>>>(s_real, s_imag);
    k_apply<<<(BB * CC) / 32, 128>>>(out);
}

// round 13
// speedup vs baseline: 1.0478x; 1.0478x over previous
#include <cuda_runtime.h>

// Problem constants
#define BB 128
#define TT 2048
#define LL 8              // timesteps per chunk
#define CC (TT / LL)      // 256 chunks per batch
#define NM (BB * TT)      // 262144 matrices total
#define DT 0.02f
#define HB (BB / 2)       // batches per pipeline half

// g_U holds intra-chunk PREFIX products: entry (b, c*8+l) = U_l...U_0 of chunk c.
__device__ __align__(128) float4 g_U[(size_t)NM * 8];        // 33.5 MB
__device__ __align__(128) float4 g_S[(size_t)BB * CC * 8];   // incoming state per chunk

// ---------------------------------------------------------------------------
// Packed f32x2 primitives (FFMA2 — only reachable via PTX)
typedef unsigned long long u64p;

__device__ __forceinline__ u64p pk2(float x, float y) {
    u64p r; asm("mov.b64 %0, {%1, %2};" : "=l"(r) : "f"(x), "f"(y)); return r;
}
__device__ __forceinline__ void upk2(u64p v, float& x, float& y) {
    asm("mov.b64 {%0, %1}, %2;" : "=f"(x), "=f"(y) : "l"(v));
}
__device__ __forceinline__ u64p psplat(float a) { return pk2(a, a); }
__device__ __forceinline__ u64p pfma(u64p a, u64p b, u64p c) {
    u64p r; asm("fma.rn.f32x2 %0, %1, %2, %3;" : "=l"(r) : "l"(a), "l"(b), "l"(c)); return r;
}
__device__ __forceinline__ u64p pmul(u64p a, u64p b) {
    u64p r; asm("mul.rn.f32x2 %0, %1, %2;" : "=l"(r) : "l"(a), "l"(b)); return r;
}
__device__ __forceinline__ u64p padd(u64p a, u64p b) {
    u64p r; asm("add.rn.f32x2 %0, %1, %2;" : "=l"(r) : "l"(a), "l"(b)); return r;
}

struct PRow { u64p r01, r23, i01, i23; };

__device__ __forceinline__ void caccum(float a, float b, const PRow& y, PRow& z) {
    u64p sa = psplat(a), sb = psplat(b), snb = psplat(-b);
    z.r01 = pfma(sa, y.r01, pfma(snb, y.i01, z.r01));
    z.r23 = pfma(sa, y.r23, pfma(snb, y.i23, z.r23));
    z.i01 = pfma(sa, y.i01, pfma(sb, y.r01, z.i01));
    z.i23 = pfma(sa, y.i23, pfma(sb, y.r23, z.i23));
}

// z_row = x_row * Y — single accumulator (R10 form; minimal live registers)
__device__ __forceinline__ PRow prow_mm(const PRow& xrow, const PRow* __restrict__ y) {
    PRow z; z.r01 = pk2(0, 0); z.r23 = pk2(0, 0); z.i01 = pk2(0, 0); z.i23 = pk2(0, 0);
    float e0, e1, e2, e3, f0, f1, f2, f3;
    upk2(xrow.r01, e0, e1); upk2(xrow.r23, e2, e3);
    upk2(xrow.i01, f0, f1); upk2(xrow.i23, f2, f3);
    caccum(e0, f0, y[0], z);
    caccum(e1, f1, y[1], z);
    caccum(e2, f2, y[2], z);
    caccum(e3, f3, y[3], z);
    return z;
}

// ---------------------------------------------------------------------------
// Scalar helpers
__device__ __forceinline__ void cax4(float a, float b, float4 cr, float4 ci,
                                     float4& accr, float4& acci) {
    accr.x = fmaf(a, cr.x, fmaf(-b, ci.x, accr.x));
    acci.x = fmaf(a, ci.x, fmaf( b, cr.x, acci.x));
    accr.y = fmaf(a, cr.y, fmaf(-b, ci.y, accr.y));
    acci.y = fmaf(a, ci.y, fmaf( b, cr.y, acci.y));
    accr.z = fmaf(a, cr.z, fmaf(-b, ci.z, accr.z));
    acci.z = fmaf(a, ci.z, fmaf( b, cr.z, acci.z));
    accr.w = fmaf(a, cr.w, fmaf(-b, ci.w, accr.w));
    acci.w = fmaf(a, ci.w, fmaf( b, cr.w, acci.w));
}

// shuffle one full float4-pair row from lane `src`
__device__ __forceinline__ void shfl_row(float4 pr, float4 pim, int src,
                                         float4& outr, float4& outi) {
    outr.x = __shfl_sync(0xffffffffu, pr.x, src);
    outr.y = __shfl_sync(0xffffffffu, pr.y, src);
    outr.z = __shfl_sync(0xffffffffu, pr.z, src);
    outr.w = __shfl_sync(0xffffffffu, pr.w, src);
    outi.x = __shfl_sync(0xffffffffu, pim.x, src);
    outi.y = __shfl_sync(0xffffffffu, pim.y, src);
    outi.z = __shfl_sync(0xffffffffu, pim.z, src);
    outi.w = __shfl_sync(0xffffffffu, pim.w, src);
}

// ---------------------------------------------------------------------------
// K0: U = expm(-i*dt*H) (degree-4 Taylor, packed f32x2), then a Kogge-Stone
// INCLUSIVE SCAN over the 8 lanes of each chunk (shfl_up): lane l ends with
// prefix_l = U_l ... U_0, stored to g_U. base = first matrix index of half.
__global__ void __launch_bounds__(128, 6) k_expm(const float* __restrict__ hr_g,
                                                 const float* __restrict__ hi_g,
                                                 int base) {
    int tid = threadIdx.x;
    int idx = base + blockIdx.x * 128 + tid;
    int el = tid & 7;

    const float4* hr4 = reinterpret_cast<const float4*>(hr_g) + (size_t)idx * 4;
    const float4* hi4 = reinterpret_cast<const float4*>(hi_g) + (size_t)idx * 4;

    // A = dt*hi - i*dt*hr
    PRow A[4];
    const u64p pdt = psplat(DT), pndt = psplat(-DT);
#pragma unroll
    for (int i = 0; i < 4; ++i) {
        float4 r = hr4[i], m = hi4[i];
        A[i].r01 = pmul(pdt,  pk2(m.x, m.y));
        A[i].r23 = pmul(pdt,  pk2(m.z, m.w));
        A[i].i01 = pmul(pndt, pk2(r.x, r.y));
        A[i].i23 = pmul(pndt, pk2(r.z, r.w));
    }

    // B = A^2 (row-wise)
    PRow B[4];
#pragma unroll
    for (int i = 0; i < 4; ++i) B[i] = prow_mm(A[i], A);

    // E = A + M·B, M = I/2 + A/6 + B/24 built row-by-row (A,B commute)
    const u64p c6 = psplat(1.0f / 6.0f), c24 = psplat(1.0f / 24.0f);
#pragma unroll
    for (int i = 0; i < 4; ++i) {
        PRow m;
        m.r01 = pfma(c6, A[i].r01, pmul(c24, B[i].r01));
        m.r23 = pfma(c6, A[i].r23, pmul(c24, B[i].r23));
        m.i01 = pfma(c6, A[i].i01, pmul(c24, B[i].i01));
        m.i23 = pfma(c6, A[i].i23, pmul(c24, B[i].i23));
        if (i == 0) m.r01 = padd(m.r01, pk2(0.5f, 0.0f));
        if (i == 1) m.r01 = padd(m.r01, pk2(0.0f, 0.5f));
        if (i == 2) m.r23 = padd(m.r23, pk2(0.5f, 0.0f));
        if (i == 3) m.r23 = padd(m.r23, pk2(0.0f, 0.5f));
        float e0, e1, e2, e3, f0, f1, f2, f3;
        upk2(m.r01, e0, e1); upk2(m.r23, e2, e3);
        upk2(m.i01, f0, f1); upk2(m.i23, f2, f3);
        caccum(e0, f0, B[0], A[i]);
        caccum(e1, f1, B[1], A[i]);
        caccum(e2, f2, B[2], A[i]);
        caccum(e3, f3, B[3], A[i]);
    }
    A[0].r01 = padd(A[0].r01, pk2(1.0f, 0.0f));
    A[1].r01 = padd(A[1].r01, pk2(0.0f, 1.0f));
    A[2].r23 = padd(A[2].r23, pk2(1.0f, 0.0f));
    A[3].r23 = padd(A[3].r23, pk2(0.0f, 1.0f));

    // ---- Kogge-Stone inclusive scan across the 8-lane chunk group.
#pragma unroll
    for (int d = 1; d < 8; d <<= 1) {
        PRow Q[4];
#pragma unroll
        for (int i = 0; i < 4; ++i) {
            Q[i].r01 = __shfl_up_sync(0xffffffffu, A[i].r01, d, 8);
            Q[i].r23 = __shfl_up_sync(0xffffffffu, A[i].r23, d, 8);
            Q[i].i01 = __shfl_up_sync(0xffffffffu, A[i].i01, d, 8);
            Q[i].i23 = __shfl_up_sync(0xffffffffu, A[i].i23, d, 8);
        }
        if (el >= d) {
#pragma unroll
            for (int i = 0; i < 4; ++i) A[i] = prow_mm(A[i], Q);
        }
    }

    // store prefix to g_U (planar: re[16] then im[16]) — coalesced
    {
        float4* Up = g_U + (size_t)idx * 8;
#pragma unroll
        for (int i = 0; i < 4; ++i) {
            float x0, x1, x2, x3;
            upk2(A[i].r01, x0, x1); upk2(A[i].r23, x2, x3);
            Up[i] = make_float4(x0, x1, x2, x3);
        }
#pragma unroll
        for (int i = 0; i < 4; ++i) {
            float x0, x1, x2, x3;
            upk2(A[i].i01, x0, x1); upk2(A[i].i23, x2, x3);
            Up[4 + i] = make_float4(x0, x1, x2, x3);
        }
    }
}

// ---------------------------------------------------------------------------
// K2: TWO-LEVEL row-parallel scan per batch (b = blockIdx.x + boff).
#define TOFF 288   // T_B offset (T matrices stride 9 quads; 32*9=288 per buffer)

__global__ void __launch_bounds__(1024) k_scan(const float* __restrict__ s0r_g,
                                               const float* __restrict__ s0i_g,
                                               int boff) {
    __shared__ float4 sh[CC * 12];   // 48KB; quads [0,576) double as T_A/T_B
    int b = blockIdx.x + boff;
    int tid = threadIdx.x;
    int e = tid >> 2, i = tid & 3;
    int lane = tid & 31;
    int el = lane >> 2;              // local chunk within warp (0..7)
    int g = e >> 3;                  // group (= warp id, 0..31)

    const float4* Pg = g_U + ((size_t)b * TT + (size_t)e * LL + (LL - 1)) * 8;
    float4 pr = Pg[i], pim = Pg[4 + i];

    // ---- L1: warp-local KS over 8 (rows fetched via shfl)
#pragma unroll
    for (int d = 1; d < 8; d <<= 1) {
        int srcb = ((el >= d) ? (el - d) : 0) << 2;
        float4 l0r, l0i, l1r, l1i, l2r, l2i, l3r, l3i;
        shfl_row(pr, pim, srcb + 0, l0r, l0i);
        shfl_row(pr, pim, srcb + 1, l1r, l1i);
        shfl_row(pr, pim, srcb + 2, l2r, l2i);
        shfl_row(pr, pim, srcb + 3, l3r, l3i);
        if (el >= d) {
            float4 nr = make_float4(0, 0, 0, 0), ni = make_float4(0, 0, 0, 0);
            cax4(pr.x, pim.x, l0r, l0i, nr, ni);
            cax4(pr.y, pim.y, l1r, l1i, nr, ni);
            cax4(pr.z, pim.z, l2r, l2i, nr, ni);
            cax4(pr.w, pim.w, l3r, l3i, nr, ni);
            pr = nr; pim = ni;
        }
    }

    // ---- publish group totals (el==7) into T_A (stride 9 quads per matrix)
    if (el == 7) {
        sh[g * 9 + i] = pr;
        sh[g * 9 + 4 + i] = pim;
    }
    __syncthreads();

    // ---- L2: KS over 32 totals, 128 threads, 5 rounds, double-buffered
    if (tid < 128) {
        int g2 = tid >> 2, i2 = tid & 3;
        int rb = 0;
#pragma unroll
        for (int d = 1; d < 32; d <<= 1) {
            const float4* src = sh + rb;
            float4* dst = sh + (TOFF - rb);
            float4 qr = src[g2 * 9 + i2], qi = src[g2 * 9 + 4 + i2];
            if (g2 >= d) {
                const float4* nb = src + (size_t)(g2 - d) * 9;
                float4 nr = make_float4(0, 0, 0, 0), ni = make_float4(0, 0, 0, 0);
                cax4(qr.x, qi.x, nb[0], nb[4], nr, ni);
                cax4(qr.y, qi.y, nb[1], nb[5], nr, ni);
                cax4(qr.z, qi.z, nb[2], nb[6], nr, ni);
                cax4(qr.w, qi.w, nb[3], nb[7], nr, ni);
                qr = nr; qi = ni;
            }
            dst[g2 * 9 + i2] = qr;
            dst[g2 * 9 + 4 + i2] = qi;
            asm volatile("bar.sync 1, 128;" ::: "memory");
            rb = TOFF - rb;
        }
    }
    __syncthreads();
    // G (inclusive group prefixes) now at sh + TOFF

    // ---- inclusive prefix: Q_e * G_{g-1}
    if (g > 0) {
        const float4* nb = sh + TOFF + (size_t)(g - 1) * 9;
        float4 nr = make_float4(0, 0, 0, 0), ni = make_float4(0, 0, 0, 0);
        cax4(pr.x, pim.x, nb[0], nb[4], nr, ni);
        cax4(pr.y, pim.y, nb[1], nb[5], nr, ni);
        cax4(pr.z, pim.z, nb[2], nb[6], nr, ni);
        cax4(pr.w, pim.w, nb[3], nb[7], nr, ni);
        pr = nr; pim = ni;
    }
    __syncthreads();   // everyone done reading T before overwriting sh below

    // ---- publish inclusive rows (XOR-swizzled layout)
    int es = e & 7;
    {
        float4* me = sh + e * 12;
        me[i ^ es] = pr;
        me[(4 + i) ^ es] = pim;
    }
    __syncthreads();

    // ---- V_e = Prefix_{e-1} * S0  (V_0 = S0)
    const float4* r4 = reinterpret_cast<const float4*>(s0r_g) + (size_t)b * 4;
    const float4* i4 = reinterpret_cast<const float4*>(s0i_g) + (size_t)b * 4;
    float4 s0r0 = r4[0], s0r1 = r4[1], s0r2 = r4[2], s0r3 = r4[3];
    float4 s0i0 = i4[0], s0i1 = i4[1], s0i2 = i4[2], s0i3 = i4[3];

    float4 vr, vi;
    if (e == 0) {
        vr = (i == 0) ? s0r0 : (i == 1) ? s0r1 : (i == 2) ? s0r2 : s0r3;
        vi = (i == 0) ? s0i0 : (i == 1) ? s0i1 : (i == 2) ? s0i2 : s0i3;
    } else {
        int ens = (e - 1) & 7;
        const float4* nb = sh + (e - 1) * 12;
        float4 qr = nb[i ^ ens];
        float4 qi = nb[(4 + i) ^ ens];
        vr = make_float4(0, 0, 0, 0); vi = make_float4(0, 0, 0, 0);
        cax4(qr.x, qi.x, s0r0, s0i0, vr, vi);
        cax4(qr.y, qi.y, s0r1, s0i1, vr, vi);
        cax4(qr.z, qi.z, s0r2, s0i2, vr, vi);
        cax4(qr.w, qi.w, s0r3, s0i3, vr, vi);
    }
    float4* Sg = g_S + ((size_t)b * CC + e) * 8;
    Sg[i] = vr;
    Sg[4 + i] = vi;
}

// ---------------------------------------------------------------------------
// K3: apply via prefixes — 8 INDEPENDENT products per thread, no smem/sync.
// Thread = (chunk, row i), batch-major within the half: warp = 8 consecutive
// b (same c) -> 512B-contiguous stores. b = (gidx & 63) + boff.
__global__ void __launch_bounds__(128) k_apply(float* __restrict__ out, int boff) {
    int tid = threadIdx.x;
    int cl = tid >> 2, i = tid & 3;
    int gidx = blockIdx.x * 32 + cl;         // b_local-fast ordering within half
    int b = (gidx & (HB - 1)) + boff;
    int c = gidx >> 6;                       // / HB
    int idx = b * CC + c;

    // full incoming state V (group-broadcast loads, L1-served)
    const float4* Vg = g_S + (size_t)idx * 8;
    float4 v0r = Vg[0], v1r = Vg[1], v2r = Vg[2], v3r = Vg[3];
    float4 v0i = Vg[4], v1i = Vg[5], v2i = Vg[6], v3i = Vg[7];

    const float4* Ug = g_U + ((size_t)b * TT + (size_t)c * LL) * 8;
    const size_t imag_off = (size_t)TT * BB * 16;
    float* ob = out + (((size_t)c * LL) * BB + b) * 16 + i * 4;

#pragma unroll
    for (int l = 0; l < LL; ++l) {
        float4 pr = Ug[l * 8 + i];           // prefix_l row i, real
        float4 pi = Ug[l * 8 + 4 + i];       // imag

        float4 nr = make_float4(0, 0, 0, 0), ni = make_float4(0, 0, 0, 0);
        cax4(pr.x, pi.x, v0r, v0i, nr, ni);
        cax4(pr.y, pi.y, v1r, v1i, nr, ni);
        cax4(pr.z, pi.z, v2r, v2i, nr, ni);
        cax4(pr.w, pi.w, v3r, v3i, nr, ni);

        float* op = ob + (size_t)l * BB * 16;
        __stcs(reinterpret_cast<float4*>(op), nr);
        __stcs(reinterpret_cast<float4*>(op + imag_off), ni);
    }
}

// ---------------------------------------------------------------------------
// Two-stream batch-halved pipeline:
//   d : expm(h0) --e0--> expm(h1), scan(h1), apply(h1)
//   s2:            e0 -> scan(h0), apply(h0) --e1--> (d waits e1)
static cudaStream_t g_s2 = nullptr;
static cudaEvent_t g_e0 = nullptr, g_e1 = nullptr;

extern "C" void kernel_launch(void* const* d_in, const int* in_sizes, int n_in,
                              void* d_out, int out_size) {
    const float* h_real = (const float*)d_in[0];
    const float* h_imag = (const float*)d_in[1];
    const float* s_real = (const float*)d_in[2];
    const float* s_imag = (const float*)d_in[3];
    float* out = (float*)d_out;

    if (g_s2 == nullptr) {   // host-resource setup, once; no device memory
        cudaStreamCreateWithFlags(&g_s2, cudaStreamNonBlocking);
        cudaEventCreateWithFlags(&g_e0, cudaEventDisableTiming);
        cudaEventCreateWithFlags(&g_e1, cudaEventDisableTiming);
    }

    const int half_mats = NM / 2;            // 131072 matrices per half

    // half 0 expm on default stream
    k_expm<<<half_mats / 128, 128>>>(h_real, h_imag, 0);
    cudaEventRecord(g_e0, 0);

    // half 0 scan+apply on side stream (overlaps with expm(h1))
    cudaStreamWaitEvent(g_s2, g_e0, 0);
    k_scan<<<HB, CC * 4, 0, g_s2>>>(s_real, s_imag, 0);
    k_apply<<<(HB * CC) / 32, 128, 0, g_s2>>>(out, 0);
    cudaEventRecord(g_e1, g_s2);

    // half 1 entirely on default stream
    k_expm<<<half_mats / 128, 128>>>(h_real, h_imag, half_mats);
    k_scan<<<HB, CC * 4>>>(s_real, s_imag, HB);
    k_apply<<<(HB * CC) / 32, 128>>>(out, HB);

    // join side stream back before returning
    cudaStreamWaitEvent(0, g_e1, 0);
}

// round 14
// speedup vs baseline: 1.2129x; 1.1576x over previous
#include <cuda_runtime.h>

// Problem constants
#define BB 128
#define TT 2048
#define LL 8              // timesteps per chunk
#define CC (TT / LL)      // 256 chunks per batch
#define NM (BB * TT)      // 262144 matrices total
#define DT 0.02f

// g_U holds intra-chunk PREFIX products: entry (b, c*8+l) = U_l...U_0 of chunk c.
__device__ __align__(128) float4 g_U[(size_t)NM * 8];        // 33.5 MB

// ---------------------------------------------------------------------------
// Packed f32x2 primitives (FFMA2 — only reachable via PTX)
typedef unsigned long long u64p;

__device__ __forceinline__ u64p pk2(float x, float y) {
    u64p r; asm("mov.b64 %0, {%1, %2};" : "=l"(r) : "f"(x), "f"(y)); return r;
}
__device__ __forceinline__ void upk2(u64p v, float& x, float& y) {
    asm("mov.b64 {%0, %1}, %2;" : "=f"(x), "=f"(y) : "l"(v));
}
__device__ __forceinline__ u64p psplat(float a) { return pk2(a, a); }
__device__ __forceinline__ u64p pfma(u64p a, u64p b, u64p c) {
    u64p r; asm("fma.rn.f32x2 %0, %1, %2, %3;" : "=l"(r) : "l"(a), "l"(b), "l"(c)); return r;
}
__device__ __forceinline__ u64p pmul(u64p a, u64p b) {
    u64p r; asm("mul.rn.f32x2 %0, %1, %2;" : "=l"(r) : "l"(a), "l"(b)); return r;
}
__device__ __forceinline__ u64p padd(u64p a, u64p b) {
    u64p r; asm("add.rn.f32x2 %0, %1, %2;" : "=l"(r) : "l"(a), "l"(b)); return r;
}

struct PRow { u64p r01, r23, i01, i23; };

__device__ __forceinline__ void caccum(float a, float b, const PRow& y, PRow& z) {
    u64p sa = psplat(a), sb = psplat(b), snb = psplat(-b);
    z.r01 = pfma(sa, y.r01, pfma(snb, y.i01, z.r01));
    z.r23 = pfma(sa, y.r23, pfma(snb, y.i23, z.r23));
    z.i01 = pfma(sa, y.i01, pfma(sb, y.r01, z.i01));
    z.i23 = pfma(sa, y.i23, pfma(sb, y.r23, z.i23));
}

// z_row = x_row * Y — single accumulator (minimal live registers)
__device__ __forceinline__ PRow prow_mm(const PRow& xrow, const PRow* __restrict__ y) {
    PRow z; z.r01 = pk2(0, 0); z.r23 = pk2(0, 0); z.i01 = pk2(0, 0); z.i23 = pk2(0, 0);
    float e0, e1, e2, e3, f0, f1, f2, f3;
    upk2(xrow.r01, e0, e1); upk2(xrow.r23, e2, e3);
    upk2(xrow.i01, f0, f1); upk2(xrow.i23, f2, f3);
    caccum(e0, f0, y[0], z);
    caccum(e1, f1, y[1], z);
    caccum(e2, f2, y[2], z);
    caccum(e3, f3, y[3], z);
    return z;
}

// ---------------------------------------------------------------------------
// Scalar helpers
__device__ __forceinline__ void cax4(float a, float b, float4 cr, float4 ci,
                                     float4& accr, float4& acci) {
    accr.x = fmaf(a, cr.x, fmaf(-b, ci.x, accr.x));
    acci.x = fmaf(a, ci.x, fmaf( b, cr.x, acci.x));
    accr.y = fmaf(a, cr.y, fmaf(-b, ci.y, accr.y));
    acci.y = fmaf(a, ci.y, fmaf( b, cr.y, acci.y));
    accr.z = fmaf(a, cr.z, fmaf(-b, ci.z, accr.z));
    acci.z = fmaf(a, ci.z, fmaf( b, cr.z, acci.z));
    accr.w = fmaf(a, cr.w, fmaf(-b, ci.w, accr.w));
    acci.w = fmaf(a, ci.w, fmaf( b, cr.w, acci.w));
}

// shuffle one full float4-pair row from lane `src`
__device__ __forceinline__ void shfl_row(float4 pr, float4 pim, int src,
                                         float4& outr, float4& outi) {
    outr.x = __shfl_sync(0xffffffffu, pr.x, src);
    outr.y = __shfl_sync(0xffffffffu, pr.y, src);
    outr.z = __shfl_sync(0xffffffffu, pr.z, src);
    outr.w = __shfl_sync(0xffffffffu, pr.w, src);
    outi.x = __shfl_sync(0xffffffffu, pim.x, src);
    outi.y = __shfl_sync(0xffffffffu, pim.y, src);
    outi.z = __shfl_sync(0xffffffffu, pim.z, src);
    outi.w = __shfl_sync(0xffffffffu, pim.w, src);
}

// ---------------------------------------------------------------------------
// K0: U = expm(-i*dt*H) (degree-4 Taylor, packed f32x2), then a Kogge-Stone
// INCLUSIVE SCAN over the 8 lanes of each chunk (shfl_up): lane l ends with
// prefix_l = U_l ... U_0, stored to g_U. No smem, no barriers.
__global__ void __launch_bounds__(128, 6) k_expm(const float* __restrict__ hr_g,
                                                 const float* __restrict__ hi_g) {
    int tid = threadIdx.x;
    int idx = blockIdx.x * 128 + tid;
    int el = tid & 7;

    const float4* hr4 = reinterpret_cast<const float4*>(hr_g) + (size_t)idx * 4;
    const float4* hi4 = reinterpret_cast<const float4*>(hi_g) + (size_t)idx * 4;

    // A = dt*hi - i*dt*hr
    PRow A[4];
    const u64p pdt = psplat(DT), pndt = psplat(-DT);
#pragma unroll
    for (int i = 0; i < 4; ++i) {
        float4 r = hr4[i], m = hi4[i];
        A[i].r01 = pmul(pdt,  pk2(m.x, m.y));
        A[i].r23 = pmul(pdt,  pk2(m.z, m.w));
        A[i].i01 = pmul(pndt, pk2(r.x, r.y));
        A[i].i23 = pmul(pndt, pk2(r.z, r.w));
    }

    // B = A^2 (row-wise)
    PRow B[4];
#pragma unroll
    for (int i = 0; i < 4; ++i) B[i] = prow_mm(A[i], A);

    // E = A + M·B, M = I/2 + A/6 + B/24 built row-by-row (A,B commute)
    const u64p c6 = psplat(1.0f / 6.0f), c24 = psplat(1.0f / 24.0f);
#pragma unroll
    for (int i = 0; i < 4; ++i) {
        PRow m;
        m.r01 = pfma(c6, A[i].r01, pmul(c24, B[i].r01));
        m.r23 = pfma(c6, A[i].r23, pmul(c24, B[i].r23));
        m.i01 = pfma(c6, A[i].i01, pmul(c24, B[i].i01));
        m.i23 = pfma(c6, A[i].i23, pmul(c24, B[i].i23));
        if (i == 0) m.r01 = padd(m.r01, pk2(0.5f, 0.0f));
        if (i == 1) m.r01 = padd(m.r01, pk2(0.0f, 0.5f));
        if (i == 2) m.r23 = padd(m.r23, pk2(0.5f, 0.0f));
        if (i == 3) m.r23 = padd(m.r23, pk2(0.0f, 0.5f));
        float e0, e1, e2, e3, f0, f1, f2, f3;
        upk2(m.r01, e0, e1); upk2(m.r23, e2, e3);
        upk2(m.i01, f0, f1); upk2(m.i23, f2, f3);
        caccum(e0, f0, B[0], A[i]);
        caccum(e1, f1, B[1], A[i]);
        caccum(e2, f2, B[2], A[i]);
        caccum(e3, f3, B[3], A[i]);
    }
    A[0].r01 = padd(A[0].r01, pk2(1.0f, 0.0f));
    A[1].r01 = padd(A[1].r01, pk2(0.0f, 1.0f));
    A[2].r23 = padd(A[2].r23, pk2(1.0f, 0.0f));
    A[3].r23 = padd(A[3].r23, pk2(0.0f, 1.0f));

    // ---- Kogge-Stone inclusive scan across the 8-lane chunk group.
#pragma unroll
    for (int d = 1; d < 8; d <<= 1) {
        PRow Q[4];
#pragma unroll
        for (int i = 0; i < 4; ++i) {
            Q[i].r01 = __shfl_up_sync(0xffffffffu, A[i].r01, d, 8);
            Q[i].r23 = __shfl_up_sync(0xffffffffu, A[i].r23, d, 8);
            Q[i].i01 = __shfl_up_sync(0xffffffffu, A[i].i01, d, 8);
            Q[i].i23 = __shfl_up_sync(0xffffffffu, A[i].i23, d, 8);
        }
        if (el >= d) {
#pragma unroll
            for (int i = 0; i < 4; ++i) A[i] = prow_mm(A[i], Q);
        }
    }

    // store prefix to g_U (planar: re[16] then im[16]) — coalesced
    {
        float4* Up = g_U + (size_t)idx * 8;
#pragma unroll
        for (int i = 0; i < 4; ++i) {
            float x0, x1, x2, x3;
            upk2(A[i].r01, x0, x1); upk2(A[i].r23, x2, x3);
            Up[i] = make_float4(x0, x1, x2, x3);
        }
#pragma unroll
        for (int i = 0; i < 4; ++i) {
            float x0, x1, x2, x3;
            upk2(A[i].i01, x0, x1); upk2(A[i].i23, x2, x3);
            Up[4 + i] = make_float4(x0, x1, x2, x3);
        }
    }
}

// ---------------------------------------------------------------------------
// K2: FUSED scan + apply per batch. 1024 threads = 256 chunks x 4 rows.
// Phase A: two-level KS scan of chunk products (prefix_7 read from g_U).
// Phase B: V_e = Prefix_{e-1} * S0 published to smem; each thread then emits
//          its chunk's 8 output rows: out[t=e*8+l] row i = prefix_l[i,:]·V_e.
#define TOFF 288   // T_B offset (T matrices stride 9 quads; 32*9=288 per buffer)

__global__ void __launch_bounds__(1024) k_scan_apply(const float* __restrict__ s0r_g,
                                                     const float* __restrict__ s0i_g,
                                                     float* __restrict__ out) {
    __shared__ float4 sh[CC * 12];   // 48KB; quads [0,576) double as T_A/T_B
    int b = blockIdx.x;
    int tid = threadIdx.x;
    int e = tid >> 2, i = tid & 3;
    int lane = tid & 31;
    int el = lane >> 2;              // local chunk within warp (0..7)
    int g = e >> 3;                  // group (= warp id, 0..31)

    const float4* Pg = g_U + ((size_t)b * TT + (size_t)e * LL + (LL - 1)) * 8;
    float4 pr = Pg[i], pim = Pg[4 + i];

    // ---- L1: warp-local KS over 8 (rows fetched via shfl)
#pragma unroll
    for (int d = 1; d < 8; d <<= 1) {
        int srcb = ((el >= d) ? (el - d) : 0) << 2;
        float4 l0r, l0i, l1r, l1i, l2r, l2i, l3r, l3i;
        shfl_row(pr, pim, srcb + 0, l0r, l0i);
        shfl_row(pr, pim, srcb + 1, l1r, l1i);
        shfl_row(pr, pim, srcb + 2, l2r, l2i);
        shfl_row(pr, pim, srcb + 3, l3r, l3i);
        if (el >= d) {
            float4 nr = make_float4(0, 0, 0, 0), ni = make_float4(0, 0, 0, 0);
            cax4(pr.x, pim.x, l0r, l0i, nr, ni);
            cax4(pr.y, pim.y, l1r, l1i, nr, ni);
            cax4(pr.z, pim.z, l2r, l2i, nr, ni);
            cax4(pr.w, pim.w, l3r, l3i, nr, ni);
            pr = nr; pim = ni;
        }
    }

    // ---- publish group totals (el==7) into T_A (stride 9 quads per matrix)
    if (el == 7) {
        sh[g * 9 + i] = pr;
        sh[g * 9 + 4 + i] = pim;
    }
    __syncthreads();

    // ---- L2: KS over 32 totals, 128 threads, 5 rounds, double-buffered
    if (tid < 128) {
        int g2 = tid >> 2, i2 = tid & 3;
        int rb = 0;
#pragma unroll
        for (int d = 1; d < 32; d <<= 1) {
            const float4* src = sh + rb;
            float4* dst = sh + (TOFF - rb);
            float4 qr = src[g2 * 9 + i2], qi = src[g2 * 9 + 4 + i2];
            if (g2 >= d) {
                const float4* nb = src + (size_t)(g2 - d) * 9;
                float4 nr = make_float4(0, 0, 0, 0), ni = make_float4(0, 0, 0, 0);
                cax4(qr.x, qi.x, nb[0], nb[4], nr, ni);
                cax4(qr.y, qi.y, nb[1], nb[5], nr, ni);
                cax4(qr.z, qi.z, nb[2], nb[6], nr, ni);
                cax4(qr.w, qi.w, nb[3], nb[7], nr, ni);
                qr = nr; qi = ni;
            }
            dst[g2 * 9 + i2] = qr;
            dst[g2 * 9 + 4 + i2] = qi;
            asm volatile("bar.sync 1, 128;" ::: "memory");
            rb = TOFF - rb;
        }
    }
    __syncthreads();
    // G (inclusive group prefixes) now at sh + TOFF

    // ---- inclusive prefix: Q_e * G_{g-1}
    if (g > 0) {
        const float4* nb = sh + TOFF + (size_t)(g - 1) * 9;
        float4 nr = make_float4(0, 0, 0, 0), ni = make_float4(0, 0, 0, 0);
        cax4(pr.x, pim.x, nb[0], nb[4], nr, ni);
        cax4(pr.y, pim.y, nb[1], nb[5], nr, ni);
        cax4(pr.z, pim.z, nb[2], nb[6], nr, ni);
        cax4(pr.w, pim.w, nb[3], nb[7], nr, ni);
        pr = nr; pim = ni;
    }
    __syncthreads();   // everyone done reading T before overwriting sh below

    // ---- publish inclusive rows (XOR-swizzled layout)
    int es = e & 7;
    {
        float4* me = sh + e * 12;
        me[i ^ es] = pr;
        me[(4 + i) ^ es] = pim;
    }
    __syncthreads();

    // ---- V_e = Prefix_{e-1} * S0  (V_0 = S0)
    const float4* r4 = reinterpret_cast<const float4*>(s0r_g) + (size_t)b * 4;
    const float4* i4 = reinterpret_cast<const float4*>(s0i_g) + (size_t)b * 4;
    float4 s0r0 = r4[0], s0r1 = r4[1], s0r2 = r4[2], s0r3 = r4[3];
    float4 s0i0 = i4[0], s0i1 = i4[1], s0i2 = i4[2], s0i3 = i4[3];

    float4 vr, vi;
    if (e == 0) {
        vr = (i == 0) ? s0r0 : (i == 1) ? s0r1 : (i == 2) ? s0r2 : s0r3;
        vi = (i == 0) ? s0i0 : (i == 1) ? s0i1 : (i == 2) ? s0i2 : s0i3;
    } else {
        int ens = (e - 1) & 7;
        const float4* nb = sh + (e - 1) * 12;
        float4 qr = nb[i ^ ens];
        float4 qi = nb[(4 + i) ^ ens];
        vr = make_float4(0, 0, 0, 0); vi = make_float4(0, 0, 0, 0);
        cax4(qr.x, qi.x, s0r0, s0i0, vr, vi);
        cax4(qr.y, qi.y, s0r1, s0i1, vr, vi);
        cax4(qr.z, qi.z, s0r2, s0i2, vr, vi);
        cax4(qr.w, qi.w, s0r3, s0i3, vr, vi);
    }

    // ---- publish V (overwrite sh, same swizzled layout), then read own chunk's V
    __syncthreads();   // all P_{e-1} reads above are done
    {
        float4* me = sh + e * 12;
        me[i ^ es] = vr;
        me[(4 + i) ^ es] = vi;
    }
    __syncthreads();

    float4 v0r, v1r, v2r, v3r, v0i, v1i, v2i, v3i;
    {
        const float4* me = sh + e * 12;
        v0r = me[0 ^ es]; v1r = me[1 ^ es]; v2r = me[2 ^ es]; v3r = me[3 ^ es];
        v0i = me[4 ^ es]; v1i = me[5 ^ es]; v2i = me[6 ^ es]; v3i = me[7 ^ es];
    }

    // ---- apply: out[t=e*8+l] row i = prefix_l[i,:] · V_e
    const float4* Ug = g_U + ((size_t)b * TT + (size_t)e * LL) * 8;
    const size_t imag_off = (size_t)TT * BB * 16;
    float* ob = out + (((size_t)e * LL) * BB + b) * 16 + i * 4;

#pragma unroll
    for (int l = 0; l < LL; ++l) {
        float4 qr = Ug[l * 8 + i];           // prefix_l row i, real
        float4 qi = Ug[l * 8 + 4 + i];       // imag

        float4 nr = make_float4(0, 0, 0, 0), ni = make_float4(0, 0, 0, 0);
        cax4(qr.x, qi.x, v0r, v0i, nr, ni);
        cax4(qr.y, qi.y, v1r, v1i, nr, ni);
        cax4(qr.z, qi.z, v2r, v2i, nr, ni);
        cax4(qr.w, qi.w, v3r, v3i, nr, ni);

        float* op = ob + (size_t)l * BB * 16;
        __stcs(reinterpret_cast<float4*>(op), nr);
        __stcs(reinterpret_cast<float4*>(op + imag_off), ni);
    }
}

// ---------------------------------------------------------------------------
extern "C" void kernel_launch(void* const* d_in, const int* in_sizes, int n_in,
                              void* d_out, int out_size) {
    const float* h_real = (const float*)d_in[0];
    const float* h_imag = (const float*)d_in[1];
    const float* s_real = (const float*)d_in[2];
    const float* s_imag = (const float*)d_in[3];
    float* out = (float*)d_out;

    k_expm<<<NM / 128, 128>>>(h_real, h_imag);
    k_scan_apply<<<BB, CC * 4>>>(s_real, s_imag, out);
}